// round 4
// baseline (speedup 1.0000x reference)
#include <cuda_runtime.h>
#include <math.h>

// ---------------------------------------------------------------------------
// 2-layer GCN:  out = log_softmax( A' @ (relu(A' @ (x@W1) + b1) @ W2) + b2 )
// A' = D^-1/2 (A + I) D^-1/2, edges scatter msg from row -> col.
// Strategy: build CSR by destination (no per-feature atomics), then
// warp-per-node aggregation with register accumulators.
// ---------------------------------------------------------------------------

#define NMAX 50000
#define EMAX 800000

__device__ int   g_is64;
__device__ int   g_cnt[NMAX];
__device__ int   g_cur[NMAX];
__device__ int   g_off[NMAX + 1];
__device__ int   g_csr[EMAX];
__device__ float g_dinv[NMAX];
__device__ float g_h1[(size_t)NMAX * 128];   // x @ W1
__device__ float g_hr[(size_t)NMAX * 128];   // relu(agg1 + b1)
__device__ float g_h2[(size_t)NMAX * 16];    // g_hr @ W2

// ---------------- index dtype handling (int32 vs int64) --------------------
__device__ __forceinline__ int get_idx(const void* p, long long i, int is64) {
    return is64 ? (int)((const long long*)p)[i] : ((const int*)p)[i];
}

// Sniff dtype: int64 little-endian values < 2^31 -> every odd 32-bit word is 0.
__global__ void detect_k(const int* __restrict__ w) {
    __shared__ int any;
    if (threadIdx.x == 0) any = 0;
    __syncthreads();
    int a = 0;
    for (int i = threadIdx.x; i < 2048; i += blockDim.x) a |= w[2 * i + 1];
    if (a) any = 1;   // benign race
    __syncthreads();
    if (threadIdx.x == 0) g_is64 = (any == 0);
}

// ---------------- degree / CSR construction --------------------------------
__global__ void init_k(int n) {
    int i = blockIdx.x * blockDim.x + threadIdx.x;
    if (i < n) { g_cnt[i] = 0; g_cur[i] = 0; }
}

__global__ void count_k(const void* __restrict__ ei, int E) {
    int e = blockIdx.x * blockDim.x + threadIdx.x;
    if (e >= E) return;
    int is64 = g_is64;
    int c = get_idx(ei, (long long)E + e, is64);
    atomicAdd(&g_cnt[c], 1);
}

__global__ void dinv_k(int n) {
    int i = blockIdx.x * blockDim.x + threadIdx.x;
    if (i < n) g_dinv[i] = rsqrtf((float)(g_cnt[i] + 1));  // +1 self loop
}

// Single-block chunked exclusive scan of g_cnt into g_off (n <= 50000).
__global__ void scan_k(int n) {
    __shared__ int s[1024];
    __shared__ int carry;
    int tid = threadIdx.x;
    if (tid == 0) carry = 0;
    __syncthreads();
    int nch = (n + 1023) / 1024;
    for (int ch = 0; ch < nch; ch++) {
        int i = ch * 1024 + tid;
        int v = (i < n) ? g_cnt[i] : 0;
        s[tid] = v;
        __syncthreads();
        for (int off = 1; off < 1024; off <<= 1) {
            int t = (tid >= off) ? s[tid - off] : 0;
            __syncthreads();
            s[tid] += t;
            __syncthreads();
        }
        if (i < n) g_off[i] = carry + s[tid] - v;
        __syncthreads();
        if (tid == 0) carry += s[1023];
        __syncthreads();
    }
    if (tid == 0) g_off[n] = carry;
}

__global__ void fill_k(const void* __restrict__ ei, int E) {
    int e = blockIdx.x * blockDim.x + threadIdx.x;
    if (e >= E) return;
    int is64 = g_is64;
    int r = get_idx(ei, (long long)e, is64);
    int c = get_idx(ei, (long long)E + e, is64);
    int p = atomicAdd(&g_cur[c], 1);
    g_csr[g_off[c] + p] = r;
}

// ---------------- GEMM1: h1 = x @ W1  (N x 128 @ 128 x 128) ----------------
// Tile 64 rows x 128 cols, 512 threads, 4x4 micro-tile. x tile in smem
// (row-major; all reads are warp-broadcast so no transpose needed).
// W1 (64 KB) stays L1/L2-resident via __ldg.
__global__ void __launch_bounds__(512) gemm1_k(const float* __restrict__ x,
                                               const float* __restrict__ W,
                                               int n) {
    __shared__ float xs[64 * 128];          // 32 KB
    int row0 = blockIdx.x * 64;
    int tid = threadIdx.x;

    // cooperative load: lane pattern gives coalesced 512B reads
    int k4 = tid & 31;          // float4 index along feature dim
    int rb = tid >> 5;          // 0..15
    for (int rr = rb; rr < 64; rr += 16) {
        int gr = row0 + rr;
        float4 v = (gr < n) ? __ldg((const float4*)&x[(size_t)gr * 128 + k4 * 4])
                            : make_float4(0.f, 0.f, 0.f, 0.f);
        *(float4*)&xs[rr * 128 + k4 * 4] = v;
    }
    __syncthreads();

    int cg = tid & 31;          // col group: cols cg*4 .. cg*4+3
    int rg = tid >> 5;          // row group: rows rg*4 .. rg*4+3
    float acc[4][4] = {};
    const float4* W4 = (const float4*)W;
    const float* xb = &xs[rg * 4 * 128];

#pragma unroll 8
    for (int k = 0; k < 128; k++) {
        float x0 = xb[0 * 128 + k];
        float x1 = xb[1 * 128 + k];
        float x2 = xb[2 * 128 + k];
        float x3 = xb[3 * 128 + k];
        float4 wv = __ldg(&W4[k * 32 + cg]);
        acc[0][0] += x0 * wv.x; acc[0][1] += x0 * wv.y; acc[0][2] += x0 * wv.z; acc[0][3] += x0 * wv.w;
        acc[1][0] += x1 * wv.x; acc[1][1] += x1 * wv.y; acc[1][2] += x1 * wv.z; acc[1][3] += x1 * wv.w;
        acc[2][0] += x2 * wv.x; acc[2][1] += x2 * wv.y; acc[2][2] += x2 * wv.z; acc[2][3] += x2 * wv.w;
        acc[3][0] += x3 * wv.x; acc[3][1] += x3 * wv.y; acc[3][2] += x3 * wv.z; acc[3][3] += x3 * wv.w;
    }

#pragma unroll
    for (int j = 0; j < 4; j++) {
        int gr = row0 + rg * 4 + j;
        if (gr < n) {
            float4 o = make_float4(acc[j][0], acc[j][1], acc[j][2], acc[j][3]);
            *(float4*)&g_h1[(size_t)gr * 128 + cg * 4] = o;
        }
    }
}

// ------------- AGG1: warp per node, hr = relu(A' @ h1 + b1) ----------------
__global__ void agg1_k(const float* __restrict__ b1, int n) {
    int warp = (blockIdx.x * blockDim.x + threadIdx.x) >> 5;
    int lane = threadIdx.x & 31;
    if (warp >= n) return;
    int c = warp;
    int s = g_off[c], e = g_off[c + 1];
    float dc = g_dinv[c];

    float4 acc = make_float4(0.f, 0.f, 0.f, 0.f);
    for (int i = s; i < e; i++) {
        int r = g_csr[i];
        float nrm = g_dinv[r] * dc;
        float4 v = *(const float4*)&g_h1[(size_t)r * 128 + lane * 4];
        acc.x += nrm * v.x; acc.y += nrm * v.y;
        acc.z += nrm * v.z; acc.w += nrm * v.w;
    }
    // self loop
    {
        float sn = dc * dc;
        float4 v = *(const float4*)&g_h1[(size_t)c * 128 + lane * 4];
        acc.x += sn * v.x; acc.y += sn * v.y;
        acc.z += sn * v.z; acc.w += sn * v.w;
    }
    float4 bb = __ldg((const float4*)&b1[lane * 4]);
    acc.x = fmaxf(acc.x + bb.x, 0.f);
    acc.y = fmaxf(acc.y + bb.y, 0.f);
    acc.z = fmaxf(acc.z + bb.z, 0.f);
    acc.w = fmaxf(acc.w + bb.w, 0.f);
    *(float4*)&g_hr[(size_t)c * 128 + lane * 4] = acc;
}

// ---------------- GEMM2: h2 = hr @ W2  (N x 128 @ 128 x 16) ----------------
__global__ void __launch_bounds__(256) gemm2_k(const float* __restrict__ W2,
                                               int n) {
    __shared__ float xs[64 * 128];          // 32 KB
    int row0 = blockIdx.x * 64;
    int tid = threadIdx.x;

    int k4 = tid & 31;
    int rb = tid >> 5;                       // 0..7
    for (int rr = rb; rr < 64; rr += 8) {
        int gr = row0 + rr;
        float4 v = (gr < n) ? *(const float4*)&g_hr[(size_t)gr * 128 + k4 * 4]
                            : make_float4(0.f, 0.f, 0.f, 0.f);
        *(float4*)&xs[rr * 128 + k4 * 4] = v;
    }
    __syncthreads();

    int c = tid & 15;            // output column 0..15
    int rg = tid >> 4;           // row group 0..15 -> rows rg*4..rg*4+3
    float acc[4] = {};
    const float* xb = &xs[rg * 4 * 128];

#pragma unroll 8
    for (int k = 0; k < 128; k++) {
        float w = __ldg(&W2[k * 16 + c]);
        acc[0] += xb[0 * 128 + k] * w;
        acc[1] += xb[1 * 128 + k] * w;
        acc[2] += xb[2 * 128 + k] * w;
        acc[3] += xb[3 * 128 + k] * w;
    }
#pragma unroll
    for (int j = 0; j < 4; j++) {
        int gr = row0 + rg * 4 + j;
        if (gr < n) g_h2[(size_t)gr * 16 + c] = acc[j];
    }
}

// --------- AGG2 + log_softmax: out = lsm(A' @ h2 + b2), warp/node ----------
__global__ void agg2_k(const float* __restrict__ b2, float* __restrict__ out,
                       int n) {
    int warp = (blockIdx.x * blockDim.x + threadIdx.x) >> 5;
    int lane = threadIdx.x & 31;
    if (warp >= n || lane >= 16) return;
    int c = warp;
    int s = g_off[c], e = g_off[c + 1];
    float dc = g_dinv[c];

    float acc = 0.f;
    for (int i = s; i < e; i++) {
        int r = g_csr[i];
        acc += g_dinv[r] * dc * g_h2[(size_t)r * 16 + lane];
    }
    acc += dc * dc * g_h2[(size_t)c * 16 + lane];
    acc += __ldg(&b2[lane]);

    // log_softmax across the 16 lanes
    float m = acc;
#pragma unroll
    for (int off = 8; off >= 1; off >>= 1)
        m = fmaxf(m, __shfl_xor_sync(0xFFFF, m, off, 16));
    float ex = expf(acc - m);
    float sum = ex;
#pragma unroll
    for (int off = 8; off >= 1; off >>= 1)
        sum += __shfl_xor_sync(0xFFFF, sum, off, 16);
    out[(size_t)c * 16 + lane] = acc - m - logf(sum);
}

// ---------------------------------------------------------------------------
extern "C" void kernel_launch(void* const* d_in, const int* in_sizes, int n_in,
                              void* d_out, int out_size) {
    const float* x  = (const float*)d_in[0];
    const void*  ei = d_in[1];
    const float* W1 = (const float*)d_in[2];
    const float* b1 = (const float*)d_in[3];
    const float* W2 = (const float*)d_in[4];
    const float* b2 = (const float*)d_in[5];
    float* out = (float*)d_out;

    int n = in_sizes[0] / 128;   // 50000
    int E = in_sizes[1] / 2;     // 800000

    detect_k<<<1, 256>>>((const int*)ei);
    init_k<<<(n + 255) / 256, 256>>>(n);
    count_k<<<(E + 255) / 256, 256>>>(ei, E);
    dinv_k<<<(n + 255) / 256, 256>>>(n);
    scan_k<<<1, 1024>>>(n);
    fill_k<<<(E + 255) / 256, 256>>>(ei, E);

    gemm1_k<<<(n + 63) / 64, 512>>>(x, W1, n);
    agg1_k<<<(n * 32 + 255) / 256, 256>>>(b1, n);
    gemm2_k<<<(n + 63) / 64, 256>>>(W2, n);
    agg2_k<<<(n * 32 + 255) / 256, 256>>>(b2, out, n);
}

// round 7
// speedup vs baseline: 1.4966x; 1.4966x over previous
#include <cuda_runtime.h>
#include <math.h>

// 2-layer GCN: out = log_softmax( A' @ (relu(A' @ (x@W1) + b1) @ W2) + b2 )
// R4: tf32 tensor-core GEMM1, parallel 3-phase scan, unrolled agg1,
//     2-nodes-per-warp agg2.

#define NMAX 50000
#define EMAX 800000
#define NBLK 64            // max scan blocks (ceil(50000/1024)=49)

__device__ int   g_is64;
__device__ int   g_cnt[NMAX];
__device__ int   g_cur[NMAX];
__device__ int   g_off[NMAX + 1];
__device__ int   g_blk[NBLK];
__device__ int   g_csr[EMAX];
__device__ float g_dinv[NMAX];
__device__ float g_h1[(size_t)NMAX * 128];   // x @ W1
__device__ float g_hr[(size_t)NMAX * 128];   // relu(agg1 + b1)
__device__ float g_h2[(size_t)NMAX * 16];    // g_hr @ W2

// ---------------- index dtype handling (int32 vs int64) --------------------
__device__ __forceinline__ int get_idx(const void* p, long long i, int is64) {
    return is64 ? (int)((const long long*)p)[i] : ((const int*)p)[i];
}

__global__ void detect_k(const int* __restrict__ w) {
    __shared__ int any;
    if (threadIdx.x == 0) any = 0;
    __syncthreads();
    int a = 0;
    for (int i = threadIdx.x; i < 2048; i += blockDim.x) a |= w[2 * i + 1];
    if (a) any = 1;
    __syncthreads();
    if (threadIdx.x == 0) g_is64 = (any == 0);
}

// ---------------- degree / CSR construction --------------------------------
__global__ void init_k(int n) {
    int i = blockIdx.x * blockDim.x + threadIdx.x;
    if (i < n) { g_cnt[i] = 0; g_cur[i] = 0; }
}

__global__ void count_k(const void* __restrict__ ei, int E) {
    int e = blockIdx.x * blockDim.x + threadIdx.x;
    if (e >= E) return;
    int c = get_idx(ei, (long long)E + e, g_is64);
    atomicAdd(&g_cnt[c], 1);
}

__global__ void dinv_k(int n) {
    int i = blockIdx.x * blockDim.x + threadIdx.x;
    if (i < n) g_dinv[i] = rsqrtf((float)(g_cnt[i] + 1));  // +1 self loop
}

// Phase A: per-block exclusive scan (1024 elems/block) + block totals.
__global__ void scanA_k(int n) {
    __shared__ int s[1024];
    int tid = threadIdx.x;
    int i = blockIdx.x * 1024 + tid;
    int v = (i < n) ? g_cnt[i] : 0;
    s[tid] = v;
    __syncthreads();
    for (int off = 1; off < 1024; off <<= 1) {
        int t = (tid >= off) ? s[tid - off] : 0;
        __syncthreads();
        s[tid] += t;
        __syncthreads();
    }
    if (i < n) g_off[i] = s[tid] - v;      // exclusive within block
    if (tid == 1023) g_blk[blockIdx.x] = s[1023];
}

// Phase B: exclusive-scan the (<=64) block totals; write grand total.
__global__ void scanB_k(int nblk, int n) {
    __shared__ int s[NBLK];
    int tid = threadIdx.x;
    if (tid < nblk) s[tid] = g_blk[tid];
    __syncthreads();
    if (tid == 0) {
        int run = 0;
        for (int b = 0; b < nblk; b++) { int t = s[b]; s[b] = run; run += t; }
        g_off[n] = run;
    }
    __syncthreads();
    if (tid < nblk) g_blk[tid] = s[tid];
}

// Phase C: add block base.
__global__ void scanC_k(int n) {
    int i = blockIdx.x * blockDim.x + threadIdx.x;
    if (i < n) g_off[i] += g_blk[i >> 10];
}

__global__ void fill_k(const void* __restrict__ ei, int E) {
    int e = blockIdx.x * blockDim.x + threadIdx.x;
    if (e >= E) return;
    int is64 = g_is64;
    int r = get_idx(ei, (long long)e, is64);
    int c = get_idx(ei, (long long)E + e, is64);
    int p = atomicAdd(&g_cur[c], 1);
    g_csr[g_off[c] + p] = r;
}

// ---------------- GEMM1 (tf32 tensor cores): h1 = x @ W1 -------------------
// Block: 128 rows x 128 cols, 256 threads (8 warps in 4x2 grid).
// Warp owns 32 rows x 64 cols = 2 m-tiles x 8 n-tiles of m16n8k8 mma.
// smem padded to stride 132 -> conflict-free fragment loads.
#define XSTR 132

__device__ __forceinline__ unsigned f2tf32(float f) {
    unsigned r;
    asm("cvt.rna.tf32.f32 %0, %1;" : "=r"(r) : "f"(f));
    return r;
}

__device__ __forceinline__ void mma_tf32(float c[4], const unsigned a[4],
                                         unsigned b0, unsigned b1) {
    asm volatile(
        "mma.sync.aligned.m16n8k8.row.col.f32.tf32.tf32.f32 "
        "{%0,%1,%2,%3}, {%4,%5,%6,%7}, {%8,%9}, {%0,%1,%2,%3};"
        : "+f"(c[0]), "+f"(c[1]), "+f"(c[2]), "+f"(c[3])
        : "r"(a[0]), "r"(a[1]), "r"(a[2]), "r"(a[3]), "r"(b0), "r"(b1));
}

__global__ void __launch_bounds__(256) gemm1_tc(const float* __restrict__ x,
                                                const float* __restrict__ W,
                                                int n) {
    extern __shared__ float sm[];
    float* xs = sm;                 // 128 x 132
    float* ws = sm + 128 * XSTR;    // 128 x 132
    int tid = threadIdx.x;
    int row0 = blockIdx.x * 128;

    // Stage W1 (tf32-converted)
    for (int i = tid; i < 128 * 32; i += 256) {
        int r = i >> 5, c4 = i & 31;
        float4 v = __ldg((const float4*)&W[r * 128 + c4 * 4]);
        float4 o;
        o.x = __uint_as_float(f2tf32(v.x)); o.y = __uint_as_float(f2tf32(v.y));
        o.z = __uint_as_float(f2tf32(v.z)); o.w = __uint_as_float(f2tf32(v.w));
        *(float4*)&ws[r * XSTR + c4 * 4] = o;
    }
    // Stage x tile (tf32-converted)
    for (int i = tid; i < 128 * 32; i += 256) {
        int r = i >> 5, c4 = i & 31;
        int gr = row0 + r;
        float4 v = (gr < n) ? __ldg((const float4*)&x[(size_t)gr * 128 + c4 * 4])
                            : make_float4(0.f, 0.f, 0.f, 0.f);
        float4 o;
        o.x = __uint_as_float(f2tf32(v.x)); o.y = __uint_as_float(f2tf32(v.y));
        o.z = __uint_as_float(f2tf32(v.z)); o.w = __uint_as_float(f2tf32(v.w));
        *(float4*)&xs[r * XSTR + c4 * 4] = o;
    }
    __syncthreads();

    int warp = tid >> 5, lane = tid & 31;
    int group = lane >> 2, tg = lane & 3;
    int ms = (warp & 3) * 32;
    int ns = (warp >> 2) * 64;

    float c[2][8][4] = {};
#pragma unroll
    for (int k0 = 0; k0 < 128; k0 += 8) {
        unsigned a[2][4];
#pragma unroll
        for (int mt = 0; mt < 2; mt++) {
            const float* ap = &xs[(ms + mt * 16 + group) * XSTR + k0 + tg];
            a[mt][0] = __float_as_uint(ap[0]);
            a[mt][1] = __float_as_uint(ap[8 * XSTR]);
            a[mt][2] = __float_as_uint(ap[4]);
            a[mt][3] = __float_as_uint(ap[8 * XSTR + 4]);
        }
#pragma unroll
        for (int nt = 0; nt < 8; nt++) {
            unsigned b0 = __float_as_uint(ws[(k0 + tg) * XSTR + ns + nt * 8 + group]);
            unsigned b1 = __float_as_uint(ws[(k0 + tg + 4) * XSTR + ns + nt * 8 + group]);
            mma_tf32(c[0][nt], a[0], b0, b1);
            mma_tf32(c[1][nt], a[1], b0, b1);
        }
    }

#pragma unroll
    for (int mt = 0; mt < 2; mt++) {
#pragma unroll
        for (int nt = 0; nt < 8; nt++) {
            int gr0 = row0 + ms + mt * 16 + group;
            int col = ns + nt * 8 + tg * 2;
            if (gr0 < n) {
                float2 o = make_float2(c[mt][nt][0], c[mt][nt][1]);
                *(float2*)&g_h1[(size_t)gr0 * 128 + col] = o;
            }
            int gr1 = gr0 + 8;
            if (gr1 < n) {
                float2 o = make_float2(c[mt][nt][2], c[mt][nt][3]);
                *(float2*)&g_h1[(size_t)gr1 * 128 + col] = o;
            }
        }
    }
}

// ------------- AGG1: warp per node, hr = relu(A' @ h1 + b1) ----------------
__global__ void agg1_k(const float* __restrict__ b1, int n) {
    int warp = (blockIdx.x * blockDim.x + threadIdx.x) >> 5;
    int lane = threadIdx.x & 31;
    if (warp >= n) return;
    int c = warp;
    int s = g_off[c], e = g_off[c + 1];
    float dc = g_dinv[c];

    float4 acc0 = make_float4(0.f, 0.f, 0.f, 0.f);
    float4 acc1 = make_float4(0.f, 0.f, 0.f, 0.f);
    int i = s;
    for (; i + 1 < e; i += 2) {
        int r0 = g_csr[i], r1 = g_csr[i + 1];
        float n0 = g_dinv[r0] * dc, n1 = g_dinv[r1] * dc;
        float4 v0 = *(const float4*)&g_h1[(size_t)r0 * 128 + lane * 4];
        float4 v1 = *(const float4*)&g_h1[(size_t)r1 * 128 + lane * 4];
        acc0.x += n0 * v0.x; acc0.y += n0 * v0.y; acc0.z += n0 * v0.z; acc0.w += n0 * v0.w;
        acc1.x += n1 * v1.x; acc1.y += n1 * v1.y; acc1.z += n1 * v1.z; acc1.w += n1 * v1.w;
    }
    if (i < e) {
        int r0 = g_csr[i];
        float n0 = g_dinv[r0] * dc;
        float4 v0 = *(const float4*)&g_h1[(size_t)r0 * 128 + lane * 4];
        acc0.x += n0 * v0.x; acc0.y += n0 * v0.y; acc0.z += n0 * v0.z; acc0.w += n0 * v0.w;
    }
    {   // self loop
        float sn = dc * dc;
        float4 v = *(const float4*)&g_h1[(size_t)c * 128 + lane * 4];
        acc0.x += sn * v.x; acc0.y += sn * v.y; acc0.z += sn * v.z; acc0.w += sn * v.w;
    }
    float4 bb = __ldg((const float4*)&b1[lane * 4]);
    float4 o;
    o.x = fmaxf(acc0.x + acc1.x + bb.x, 0.f);
    o.y = fmaxf(acc0.y + acc1.y + bb.y, 0.f);
    o.z = fmaxf(acc0.z + acc1.z + bb.z, 0.f);
    o.w = fmaxf(acc0.w + acc1.w + bb.w, 0.f);
    *(float4*)&g_hr[(size_t)c * 128 + lane * 4] = o;
}

// ---------------- GEMM2: h2 = hr @ W2  (N x 128 @ 128 x 16) ----------------
__global__ void __launch_bounds__(256) gemm2_k(const float* __restrict__ W2,
                                               int n) {
    __shared__ float xs[64 * 128];
    int row0 = blockIdx.x * 64;
    int tid = threadIdx.x;

    int k4 = tid & 31;
    int rb = tid >> 5;
    for (int rr = rb; rr < 64; rr += 8) {
        int gr = row0 + rr;
        float4 v = (gr < n) ? *(const float4*)&g_hr[(size_t)gr * 128 + k4 * 4]
                            : make_float4(0.f, 0.f, 0.f, 0.f);
        *(float4*)&xs[rr * 128 + k4 * 4] = v;
    }
    __syncthreads();

    int c = tid & 15;
    int rg = tid >> 4;
    float acc[4] = {};
    const float* xb = &xs[rg * 4 * 128];

#pragma unroll 8
    for (int k = 0; k < 128; k++) {
        float w = __ldg(&W2[k * 16 + c]);
        acc[0] += xb[0 * 128 + k] * w;
        acc[1] += xb[1 * 128 + k] * w;
        acc[2] += xb[2 * 128 + k] * w;
        acc[3] += xb[3 * 128 + k] * w;
    }
#pragma unroll
    for (int j = 0; j < 4; j++) {
        int gr = row0 + rg * 4 + j;
        if (gr < n) g_h2[(size_t)gr * 16 + c] = acc[j];
    }
}

// ---- AGG2 + log_softmax, 2 nodes per warp (16 lanes each) -----------------
__global__ void agg2_k(const float* __restrict__ b2, float* __restrict__ out,
                       int n) {
    int gtid = blockIdx.x * blockDim.x + threadIdx.x;
    int node = gtid >> 4;
    int lane16 = gtid & 15;
    if (node >= n) return;
    unsigned mask = 0xFFFFu << (threadIdx.x & 16);

    int s = g_off[node], e = g_off[node + 1];
    float dc = g_dinv[node];

    float acc = 0.f;
    for (int i = s; i < e; i++) {
        int r = g_csr[i];
        acc += g_dinv[r] * dc * g_h2[(size_t)r * 16 + lane16];
    }
    acc += dc * dc * g_h2[(size_t)node * 16 + lane16];
    acc += __ldg(&b2[lane16]);

    float m = acc;
#pragma unroll
    for (int off = 8; off >= 1; off >>= 1)
        m = fmaxf(m, __shfl_xor_sync(mask, m, off, 16));
    float ex = expf(acc - m);
    float sum = ex;
#pragma unroll
    for (int off = 8; off >= 1; off >>= 1)
        sum += __shfl_xor_sync(mask, sum, off, 16);
    out[(size_t)node * 16 + lane16] = acc - m - logf(sum);
}

// ---------------------------------------------------------------------------
extern "C" void kernel_launch(void* const* d_in, const int* in_sizes, int n_in,
                              void* d_out, int out_size) {
    const float* x  = (const float*)d_in[0];
    const void*  ei = d_in[1];
    const float* W1 = (const float*)d_in[2];
    const float* b1 = (const float*)d_in[3];
    const float* W2 = (const float*)d_in[4];
    const float* b2 = (const float*)d_in[5];
    float* out = (float*)d_out;

    int n = in_sizes[0] / 128;   // 50000
    int E = in_sizes[1] / 2;     // 800000

    int nblk = (n + 1023) / 1024;

    cudaFuncSetAttribute(gemm1_tc, cudaFuncAttributeMaxDynamicSharedMemorySize,
                         2 * 128 * XSTR * (int)sizeof(float));

    detect_k<<<1, 256>>>((const int*)ei);
    init_k<<<(n + 255) / 256, 256>>>(n);
    count_k<<<(E + 255) / 256, 256>>>(ei, E);
    dinv_k<<<(n + 255) / 256, 256>>>(n);
    scanA_k<<<nblk, 1024>>>(n);
    scanB_k<<<1, NBLK>>>(nblk, n);
    scanC_k<<<(n + 255) / 256, 256>>>(n);
    fill_k<<<(E + 255) / 256, 256>>>(ei, E);

    gemm1_tc<<<(n + 127) / 128, 256, 2 * 128 * XSTR * (int)sizeof(float)>>>(x, W1, n);
    agg1_k<<<(n * 32 + 255) / 256, 256>>>(b1, n);
    gemm2_k<<<(n + 63) / 64, 256>>>(W2, n);
    agg2_k<<<(n * 16 + 255) / 256, 256>>>(b2, out, n);
}